// round 1
// baseline (speedup 1.0000x reference)
#include <cuda_runtime.h>
#include <cmath>

#define DD 160
#define HH 160
#define WW 160
#define NB 2
#define HW_ (HH * WW)
#define DHW_ (DD * HH * WW)          // 4,096,000
#define NVOX (NB * DHW_)             // 8,192,000
#define NROWS (NB * DD * HH)         // 51,200

struct G7 { float g[7]; };

// Scratch: 5 fields x 2 batch volumes, conv'd in place across passes (163.84 MB)
__device__ float g_buf[10u * DHW_];
// Per-row SSIM partial sums
__device__ float g_partials[NROWS];

// ---------------------------------------------------------------------------
// Pass 1: convolve along D. Compute the 5 linear fields {p,t,p^2,t^2,p*t}
// on the fly from the two inputs. Each thread owns a d-chunk of one (n,h,w)
// column, with a 7-wide rolling register window per field (1 load/element).
// ---------------------------------------------------------------------------
__global__ void pass1_kernel(const float* __restrict__ p,
                             const float* __restrict__ t,
                             G7 gw, int chunks, int L) {
    int tid = blockIdx.x * blockDim.x + threadIdx.x;
    const int ncol = NB * HH * WW;
    if (tid >= ncol * chunks) return;
    int col = tid % ncol;     // consecutive threads -> consecutive w (coalesced)
    int ci  = tid / ncol;
    int d0  = ci * L;
    int w   = col % WW;
    int rem = col / WW;
    int h   = rem % HH;
    int n   = rem / HH;
    long base = (long)n * DHW_ + (long)h * WW + w;

    float win[5][7];
#pragma unroll
    for (int k = 0; k < 7; ++k) {
        int d = d0 - 3 + k;
        float a = 0.f, b = 0.f;
        if (d >= 0 && d < DD) {
            a = p[base + (long)d * HW_];
            b = t[base + (long)d * HW_];
        }
        win[0][k] = a; win[1][k] = b;
        win[2][k] = a * a; win[3][k] = b * b; win[4][k] = a * b;
    }

    for (int d = d0; d < d0 + L; ++d) {
#pragma unroll
        for (int f = 0; f < 5; ++f) {
            float acc = 0.f;
#pragma unroll
            for (int k = 0; k < 7; ++k) acc = fmaf(gw.g[k], win[f][k], acc);
            g_buf[(long)(f * NB + n) * DHW_ + (long)d * HW_ + (long)h * WW + w] = acc;
        }
#pragma unroll
        for (int f = 0; f < 5; ++f)
#pragma unroll
            for (int k = 0; k < 6; ++k) win[f][k] = win[f][k + 1];
        int dn = d + 4;
        float a = 0.f, b = 0.f;
        if (dn < DD) {
            a = p[base + (long)dn * HW_];
            b = t[base + (long)dn * HW_];
        }
        win[0][6] = a; win[1][6] = b;
        win[2][6] = a * a; win[3][6] = b * b; win[4][6] = a * b;
    }
}

// ---------------------------------------------------------------------------
// Pass 2: convolve along H, in place on g_buf. Safe: each thread owns a full
// h-column; the rolling window reads h+4 strictly after writing h (writes
// never land ahead of any future read). 256,000 independent columns.
// ---------------------------------------------------------------------------
__global__ void pass2_kernel(G7 gw) {
    int tid = blockIdx.x * blockDim.x + threadIdx.x;
    const int ncol = 10 * DD * WW;   // 256,000
    if (tid >= ncol) return;
    int w   = tid % WW;              // consecutive threads -> consecutive w
    int rem = tid / WW;
    int d   = rem % DD;
    int vol = rem / DD;
    long base = ((long)vol * DD + d) * HW_ + w;

    float win[7];
#pragma unroll
    for (int k = 0; k < 7; ++k) {
        int h = k - 3;
        win[k] = (h >= 0) ? g_buf[base + (long)h * WW] : 0.f;
    }
    for (int h = 0; h < HH; ++h) {
        float acc = 0.f;
#pragma unroll
        for (int k = 0; k < 7; ++k) acc = fmaf(gw.g[k], win[k], acc);
        g_buf[base + (long)h * WW] = acc;
#pragma unroll
        for (int k = 0; k < 6; ++k) win[k] = win[k + 1];
        int hn = h + 4;
        win[6] = (hn < HH) ? g_buf[base + (long)hn * WW] : 0.f;
    }
}

// ---------------------------------------------------------------------------
// Pass 3: one block per (n,d,h) row. Load the 5 field rows into smem with a
// zero halo, do the 7-tap W-conv from smem, evaluate the SSIM map, and do a
// fixed-order block reduction to one partial per row.
// ---------------------------------------------------------------------------
__global__ void pass3_kernel(G7 gw) {
    __shared__ float srow[5][WW + 6];
    __shared__ float sred[WW];
    int bid = blockIdx.x;
    int h   = bid % HH;
    int rem = bid / HH;
    int d   = rem % DD;
    int n   = rem / DD;
    int tid = threadIdx.x;   // 0..159

    long rowbase = (long)d * HW_ + (long)h * WW;
#pragma unroll
    for (int f = 0; f < 5; ++f)
        srow[f][3 + tid] = g_buf[(long)(f * NB + n) * DHW_ + rowbase + tid];
    if (tid < 3) {
#pragma unroll
        for (int f = 0; f < 5; ++f) {
            srow[f][tid] = 0.f;
            srow[f][WW + 3 + tid] = 0.f;
        }
    }
    __syncthreads();

    float c[5];
#pragma unroll
    for (int f = 0; f < 5; ++f) {
        float acc = 0.f;
#pragma unroll
        for (int k = 0; k < 7; ++k) acc = fmaf(gw.g[k], srow[f][tid + k], acc);
        c[f] = acc;
    }
    float mu1 = c[0], mu2 = c[1];
    float mu1s = mu1 * mu1, mu2s = mu2 * mu2, mu12 = mu1 * mu2;
    float s1 = c[2] - mu1s, s2 = c[3] - mu2s, s12 = c[4] - mu12;
    const float C1v = 1e-4f;   // 0.01^2
    const float C2v = 9e-4f;   // 0.03^2
    float num = (2.f * mu12 + C1v) * (2.f * s12 + C2v);
    float den = (mu1s + mu2s + C1v) * (s1 + s2 + C2v);
    sred[tid] = num / den;
    __syncthreads();

    for (int s = 128; s > 0; s >>= 1) {
        if (tid < s && tid + s < WW) sred[tid] += sred[tid + s];
        __syncthreads();
    }
    if (tid == 0) g_partials[bid] = sred[0];
}

// ---------------------------------------------------------------------------
// Final: deterministic single-block double-precision reduction of row
// partials -> out[0] = 1 - mean(ssim_map)
// ---------------------------------------------------------------------------
__global__ void reduce_kernel(float* __restrict__ out) {
    __shared__ double sm[1024];
    int tid = threadIdx.x;
    double acc = 0.0;
    for (int i = tid; i < NROWS; i += 1024) acc += (double)g_partials[i];
    sm[tid] = acc;
    __syncthreads();
    for (int s = 512; s > 0; s >>= 1) {
        if (tid < s) sm[tid] += sm[tid + s];
        __syncthreads();
    }
    if (tid == 0) out[0] = 1.f - (float)(sm[0] / (double)NVOX);
}

extern "C" void kernel_launch(void* const* d_in, const int* in_sizes, int n_in,
                              void* d_out, int out_size) {
    const float* p = (const float*)d_in[0];
    const float* t = (const float*)d_in[1];
    float* out = (float*)d_out;

    // 1D Gaussian, sigma = ws/6 (separable; reference's double normalization
    // is identity since sum(g)=1)
    G7 gw;
    double gd[7], s = 0.0;
    const double sigma = 7.0 / 6.0;
    for (int i = 0; i < 7; ++i) {
        double x = (double)(i - 3);
        gd[i] = exp(-x * x / (2.0 * sigma * sigma));
        s += gd[i];
    }
    for (int i = 0; i < 7; ++i) gw.g[i] = (float)(gd[i] / s);

    const int chunks = 4, L = DD / chunks;
    int th1 = NB * HH * WW * chunks;                       // 204,800
    pass1_kernel<<<(th1 + 255) / 256, 256>>>(p, t, gw, chunks, L);
    pass2_kernel<<<(10 * DD * WW + 255) / 256, 256>>>(gw); // 256,000 threads
    pass3_kernel<<<NROWS, WW>>>(gw);
    reduce_kernel<<<1, 1024>>>(out);
}

// round 2
// speedup vs baseline: 1.4928x; 1.4928x over previous
#include <cuda_runtime.h>
#include <cmath>

#define DD 160
#define HH 160
#define WW 160
#define NB 2
#define HW_ (HH * WW)
#define DHW_ (DD * HH * WW)          // 4,096,000
#define NVOX (NB * DHW_)             // 8,192,000
#define HCH 2                        // h-chunks in fused pass
#define HL  (HH / HCH)               // 80
#define NPART (NB * DD * HCH)        // 640 partials

struct G7 { float g[7]; };

// Scratch: 5 conv-d fields x 2 batches (163.84 MB)
__device__ float g_buf[10u * DHW_];
__device__ float g_partials[NPART];

// ---------------------------------------------------------------------------
// Pass 1: convolve along D. Compute the 5 linear fields {p,t,p^2,t^2,p*t}
// on the fly. Thread owns a d-chunk of one (n,h,w) column; rolling 7-deep
// register windows (1 load/elem/input).
// ---------------------------------------------------------------------------
__global__ void pass1_kernel(const float* __restrict__ p,
                             const float* __restrict__ t,
                             G7 gw, int chunks, int L) {
    int tid = blockIdx.x * blockDim.x + threadIdx.x;
    const int ncol = NB * HH * WW;
    if (tid >= ncol * chunks) return;
    int col = tid % ncol;     // consecutive threads -> consecutive w
    int ci  = tid / ncol;
    int d0  = ci * L;
    int w   = col % WW;
    int rem = col / WW;
    int h   = rem % HH;
    int n   = rem / HH;
    long base = (long)n * DHW_ + (long)h * WW + w;

    float win[5][7];
#pragma unroll
    for (int k = 0; k < 7; ++k) {
        int d = d0 - 3 + k;
        float a = 0.f, b = 0.f;
        if (d >= 0 && d < DD) {
            a = p[base + (long)d * HW_];
            b = t[base + (long)d * HW_];
        }
        win[0][k] = a; win[1][k] = b;
        win[2][k] = a * a; win[3][k] = b * b; win[4][k] = a * b;
    }

    for (int d = d0; d < d0 + L; ++d) {
#pragma unroll
        for (int f = 0; f < 5; ++f) {
            float acc = 0.f;
#pragma unroll
            for (int k = 0; k < 7; ++k) acc = fmaf(gw.g[k], win[f][k], acc);
            g_buf[(long)(f * NB + n) * DHW_ + (long)d * HW_ + (long)h * WW + w] = acc;
        }
#pragma unroll
        for (int f = 0; f < 5; ++f)
#pragma unroll
            for (int k = 0; k < 6; ++k) win[f][k] = win[f][k + 1];
        int dn = d + 4;
        float a = 0.f, b = 0.f;
        if (dn < DD) {
            a = p[base + (long)dn * HW_];
            b = t[base + (long)dn * HW_];
        }
        win[0][6] = a; win[1][6] = b;
        win[2][6] = a * a; win[3][6] = b * b; win[4][6] = a * b;
    }
}

// ---------------------------------------------------------------------------
// Fused pass 2+3: H-conv (rolling register windows over the 5 conv-d fields)
// + W-conv (via double-buffered smem plane) + SSIM map + in-block reduction.
// Block = (n, d, h-chunk), 160 threads = one w-row. One sync per h-step.
// ---------------------------------------------------------------------------
__global__ void __launch_bounds__(WW) fused23_kernel(G7 gw) {
    __shared__ float plane[2][5][WW + 6];
    __shared__ float sred[WW];
    int bid = blockIdx.x;
    int ch  = bid % HCH;
    int d   = (bid / HCH) % DD;
    int n   = bid / (HCH * DD);
    int w   = threadIdx.x;   // 0..159
    int h0  = ch * HL;

    // zero smem halos once (never overwritten)
    if (w < 3) {
#pragma unroll
        for (int b = 0; b < 2; ++b)
#pragma unroll
            for (int f = 0; f < 5; ++f) {
                plane[b][f][w] = 0.f;
                plane[b][f][WW + 3 + w] = 0.f;
            }
    }

    long base = (long)d * HW_ + w;     // + (f*NB+n)*DHW_ + row*WW

    // prime 7-deep h-windows for 5 fields
    float win[5][7];
#pragma unroll
    for (int k = 0; k < 7; ++k) {
        int row = h0 - 3 + k;
        bool v = (row >= 0) && (row < HH);
        long off = base + (long)(v ? row : 0) * WW;
#pragma unroll
        for (int f = 0; f < 5; ++f)
            win[f][k] = v ? g_buf[(long)(f * NB + n) * DHW_ + off] : 0.f;
    }
    __syncthreads();

    float acc_ssim = 0.f;
    const float C1v = 1e-4f, C2v = 9e-4f;

    for (int i = 0; i < HL; ++i) {
        int h = h0 + i;
        int buf = i & 1;

        // prefetch next row (independent of smem) before the barrier
        int hn = h + 4;
        bool v = (hn < HH);
        long off = base + (long)(v ? hn : 0) * WW;
        float nxt[5];
#pragma unroll
        for (int f = 0; f < 5; ++f)
            nxt[f] = v ? g_buf[(long)(f * NB + n) * DHW_ + off] : 0.f;

        // conv-h from register windows -> smem plane
#pragma unroll
        for (int f = 0; f < 5; ++f) {
            float acc = 0.f;
#pragma unroll
            for (int k = 0; k < 7; ++k) acc = fmaf(gw.g[k], win[f][k], acc);
            plane[buf][f][w + 3] = acc;
        }
        __syncthreads();

        // conv-w + SSIM
        float c[5];
#pragma unroll
        for (int f = 0; f < 5; ++f) {
            float acc = 0.f;
#pragma unroll
            for (int k = 0; k < 7; ++k) acc = fmaf(gw.g[k], plane[buf][f][w + k], acc);
            c[f] = acc;
        }
        float mu1 = c[0], mu2 = c[1];
        float mu1s = mu1 * mu1, mu2s = mu2 * mu2, mu12 = mu1 * mu2;
        float s1 = c[2] - mu1s, s2 = c[3] - mu2s, s12 = c[4] - mu12;
        float num = (2.f * mu12 + C1v) * (2.f * s12 + C2v);
        float den = (mu1s + mu2s + C1v) * (s1 + s2 + C2v);
        acc_ssim += num / den;

        // shift windows, insert prefetched row
#pragma unroll
        for (int f = 0; f < 5; ++f) {
#pragma unroll
            for (int k = 0; k < 6; ++k) win[f][k] = win[f][k + 1];
            win[f][6] = nxt[f];
        }
    }

    // fixed-order block reduction
    sred[w] = acc_ssim;
    __syncthreads();
    for (int s = 128; s > 0; s >>= 1) {
        if (w < s && w + s < WW) sred[w] += sred[w + s];
        __syncthreads();
    }
    if (w == 0) g_partials[bid] = sred[0];
}

// ---------------------------------------------------------------------------
// Final: deterministic single-block reduction of 640 partials (double)
// ---------------------------------------------------------------------------
__global__ void reduce_kernel(float* __restrict__ out) {
    __shared__ double sm[256];
    int tid = threadIdx.x;
    double acc = 0.0;
    for (int i = tid; i < NPART; i += 256) acc += (double)g_partials[i];
    sm[tid] = acc;
    __syncthreads();
    for (int s = 128; s > 0; s >>= 1) {
        if (tid < s) sm[tid] += sm[tid + s];
        __syncthreads();
    }
    if (tid == 0) out[0] = 1.f - (float)(sm[0] / (double)NVOX);
}

extern "C" void kernel_launch(void* const* d_in, const int* in_sizes, int n_in,
                              void* d_out, int out_size) {
    const float* p = (const float*)d_in[0];
    const float* t = (const float*)d_in[1];
    float* out = (float*)d_out;

    // 1D Gaussian, sigma = ws/6 (separable; double normalization is identity)
    G7 gw;
    double gd[7], s = 0.0;
    const double sigma = 7.0 / 6.0;
    for (int i = 0; i < 7; ++i) {
        double x = (double)(i - 3);
        gd[i] = exp(-x * x / (2.0 * sigma * sigma));
        s += gd[i];
    }
    for (int i = 0; i < 7; ++i) gw.g[i] = (float)(gd[i] / s);

    const int chunks = 4, L = DD / chunks;
    int th1 = NB * HH * WW * chunks;                       // 204,800
    pass1_kernel<<<(th1 + 255) / 256, 256>>>(p, t, gw, chunks, L);
    fused23_kernel<<<NB * DD * HCH, WW>>>(gw);             // 640 blocks
    reduce_kernel<<<1, 256>>>(out);
}

// round 3
// speedup vs baseline: 1.8395x; 1.2322x over previous
#include <cuda_runtime.h>
#include <cuda_fp16.h>

#define DD 160
#define HH 160
#define WW 160
#define NB 2
#define HW_ (HH * WW)
#define DHW_ (DD * HH * WW)          // 4,096,000
#define NVOX (NB * DHW_)             // 8,192,000
#define HCH 4
#define HL  (HH / HCH)               // 40
#define NPART (NB * DD * HCH)        // 1280

// Gaussian weights for sigma = 7/6, computed to ~1e-7 (compile-time literals
// so ptxas emits FFMA-imm, rt=1)
#define G0 0.0125602f
#define G1 0.0788279f
#define G2 0.2372961f
#define G3 0.3426315f
__device__ __forceinline__ float gk(int k) {
    constexpr float g[7] = {G0, G1, G2, G3, G2, G1, G0};
    return g[k];
}
// Border valid-weight factor per axis (zero-padding mass correction)
__device__ __forceinline__ float bfac(int i) {
    float f = 1.f;
    if (i < 3)   f -= (i == 2 ? G0 : (i == 1 ? (G0 + G1) : (G0 + G1 + G2)));
    if (i > 156) f -= (i == 157 ? G0 : (i == 158 ? (G0 + G1) : (G0 + G1 + G2)));
    return f;
}

// fp16 scratch: 5 shifted fields x 2 batches (81.92 MB)
__device__ __half g_buf[10u * DHW_];
__device__ float g_partials[NPART];

// ---------------------------------------------------------------------------
// Pass 1: conv along D of {q, r, q^2, r^2, qr}, q=p-1/2, r=t-1/2. Rolling
// 7-deep register windows, fp16 stores.
// ---------------------------------------------------------------------------
__global__ void __launch_bounds__(256) pass1_kernel(const float* __restrict__ p,
                                                    const float* __restrict__ t,
                                                    int chunks, int L) {
    int tid = blockIdx.x * blockDim.x + threadIdx.x;
    const int ncol = NB * HH * WW;
    if (tid >= ncol * chunks) return;
    int col = tid % ncol;     // consecutive threads -> consecutive w
    int ci  = tid / ncol;
    int d0  = ci * L;
    int w   = col % WW;
    int rem = col / WW;
    int h   = rem % HH;
    int n   = rem / HH;
    long base = (long)n * DHW_ + (long)h * WW + w;

    float win[5][7];
#pragma unroll
    for (int k = 0; k < 7; ++k) {
        int d = d0 - 3 + k;
        float a = 0.f, b = 0.f;
        if (d >= 0 && d < DD) {
            a = p[base + (long)d * HW_] - 0.5f;
            b = t[base + (long)d * HW_] - 0.5f;
        }
        win[0][k] = a; win[1][k] = b;
        win[2][k] = a * a; win[3][k] = b * b; win[4][k] = a * b;
    }

#pragma unroll 4
    for (int d = d0; d < d0 + L; ++d) {
        long ob = (long)n * DHW_ + (long)d * HW_ + (long)h * WW + w;
#pragma unroll
        for (int f = 0; f < 5; ++f) {
            float acc = 0.f;
#pragma unroll
            for (int k = 0; k < 7; ++k) acc = fmaf(gk(k), win[f][k], acc);
            g_buf[(long)(f * NB) * DHW_ + ob] = __float2half_rn(acc);
        }
#pragma unroll
        for (int f = 0; f < 5; ++f)
#pragma unroll
            for (int k = 0; k < 6; ++k) win[f][k] = win[f][k + 1];
        int dn = d + 4;
        float a = 0.f, b = 0.f;
        if (dn < DD) {
            a = p[base + (long)dn * HW_] - 0.5f;
            b = t[base + (long)dn * HW_] - 0.5f;
        }
        win[0][6] = a; win[1][6] = b;
        win[2][6] = a * a; win[3][6] = b * b; win[4][6] = a * b;
    }
}

// ---------------------------------------------------------------------------
// Fused pass 2+3: H-conv (rolling register windows) + W-conv (double-buffered
// smem plane) + exact border reconstruction + SSIM + in-block reduction.
// Block = (n, d, h-chunk of 40), 160 threads = one w-row.
// ---------------------------------------------------------------------------
__global__ void __launch_bounds__(WW) fused23_kernel() {
    __shared__ float plane[2][5][WW + 6];
    __shared__ float sred[WW];
    int bid = blockIdx.x;
    int ch  = bid % HCH;
    int d   = (bid / HCH) % DD;
    int n   = bid / (HCH * DD);
    int w   = threadIdx.x;   // 0..159
    int h0  = ch * HL;

    if (w < 3) {
#pragma unroll
        for (int b = 0; b < 2; ++b)
#pragma unroll
            for (int f = 0; f < 5; ++f) {
                plane[b][f][w] = 0.f;
                plane[b][f][WW + 3 + w] = 0.f;
            }
    }

    float wdw = bfac(d) * bfac(w);       // per-thread constant part of W
    long base = (long)d * HW_ + w;

    float win[5][7];
#pragma unroll
    for (int k = 0; k < 7; ++k) {
        int row = h0 - 3 + k;
        bool v = (row >= 0) && (row < HH);
        long off = base + (long)(v ? row : 0) * WW;
#pragma unroll
        for (int f = 0; f < 5; ++f)
            win[f][k] = v ? __half2float(g_buf[(long)(f * NB + n) * DHW_ + off]) : 0.f;
    }
    __syncthreads();

    float acc_ssim = 0.f;
    const float C1v = 1e-4f, C2v = 9e-4f;

#pragma unroll 4
    for (int i = 0; i < HL; ++i) {
        int h = h0 + i;
        int buf = i & 1;

        // prefetch next row before the barrier
        int hn = h + 4;
        bool v = (hn < HH);
        long off = base + (long)(v ? hn : 0) * WW;
        float nxt[5];
#pragma unroll
        for (int f = 0; f < 5; ++f)
            nxt[f] = v ? __half2float(g_buf[(long)(f * NB + n) * DHW_ + off]) : 0.f;

        // conv-h -> smem plane
#pragma unroll
        for (int f = 0; f < 5; ++f) {
            float acc = 0.f;
#pragma unroll
            for (int k = 0; k < 7; ++k) acc = fmaf(gk(k), win[f][k], acc);
            plane[buf][f][w + 3] = acc;
        }
        __syncthreads();

        // conv-w
        float c[5];
#pragma unroll
        for (int f = 0; f < 5; ++f) {
            float acc = 0.f;
#pragma unroll
            for (int k = 0; k < 7; ++k) acc = fmaf(gk(k), plane[buf][f][w + k], acc);
            c[f] = acc;
        }

        // exact reconstruction from shifted fields (zero-padding mass W)
        float W = wdw * bfac(h);
        float mu1 = c[0] + 0.5f * W;
        float mu2 = c[1] + 0.5f * W;
        float Ep2 = c[2] + mu1 - 0.25f * W;
        float Et2 = c[3] + mu2 - 0.25f * W;
        float Ept = c[4] + 0.5f * (mu1 + mu2) - 0.25f * W;
        float mu1s = mu1 * mu1, mu2s = mu2 * mu2, mu12 = mu1 * mu2;
        float s1 = Ep2 - mu1s, s2 = Et2 - mu2s, s12 = Ept - mu12;
        float num = (2.f * mu12 + C1v) * (2.f * s12 + C2v);
        float den = (mu1s + mu2s + C1v) * (s1 + s2 + C2v);
        acc_ssim += num / den;

#pragma unroll
        for (int f = 0; f < 5; ++f) {
#pragma unroll
            for (int k = 0; k < 6; ++k) win[f][k] = win[f][k + 1];
            win[f][6] = nxt[f];
        }
    }

    sred[w] = acc_ssim;
    __syncthreads();
    for (int s = 128; s > 0; s >>= 1) {
        if (w < s && w + s < WW) sred[w] += sred[w + s];
        __syncthreads();
    }
    if (w == 0) g_partials[bid] = sred[0];
}

// ---------------------------------------------------------------------------
// Final deterministic reduction of 1280 partials
// ---------------------------------------------------------------------------
__global__ void reduce_kernel(float* __restrict__ out) {
    __shared__ double sm[256];
    int tid = threadIdx.x;
    double acc = 0.0;
    for (int i = tid; i < NPART; i += 256) acc += (double)g_partials[i];
    sm[tid] = acc;
    __syncthreads();
    for (int s = 128; s > 0; s >>= 1) {
        if (tid < s) sm[tid] += sm[tid + s];
        __syncthreads();
    }
    if (tid == 0) out[0] = 1.f - (float)(sm[0] / (double)NVOX);
}

extern "C" void kernel_launch(void* const* d_in, const int* in_sizes, int n_in,
                              void* d_out, int out_size) {
    const float* p = (const float*)d_in[0];
    const float* t = (const float*)d_in[1];
    float* out = (float*)d_out;

    const int chunks = 4, L = DD / chunks;
    int th1 = NB * HH * WW * chunks;                        // 204,800
    pass1_kernel<<<(th1 + 255) / 256, 256>>>(p, t, chunks, L);
    fused23_kernel<<<NB * DD * HCH, WW>>>();                // 1280 blocks
    reduce_kernel<<<1, 256>>>(out);
}